// round 2
// baseline (speedup 1.0000x reference)
#include <cuda_runtime.h>
#include <cstdint>

// Problem constants (fixed by dataset):
//   x      [B=4, C=64, T=1000, F=96]  f32
//   weight [F=96, C*5=320, O=2]       f32   (flattened (C,tc) C-major: idx = c*5+k)
//   bias   [F=96, O=2]                f32
//   out    [B=4, O=2, T=1000, F=96]   f32
// out[b,o,t,f] = sum_{c,k} x[b,c,t-4+k,f] * w[f, c*5+k, o] + bias[f,o]   (x zero-padded t<0)

#define FD 96
#define CD 64
#define TD 1000
#define TC 5
#define TPG 5                  // t per thread
#define TT 10                  // t per block (2 t-groups)
#define NTHREADS 192           // 96 f-lanes x 2 t-groups
#define NTILES (TD / TT)       // 100
#define WROWS (TPG + TC - 1)   // 9 window rows per thread

typedef unsigned long long u64;

__device__ __forceinline__ u64 pack2(float lo, float hi) {
    u64 r;
    asm("mov.b64 %0, {%1, %2};" : "=l"(r) : "f"(lo), "f"(hi));
    return r;
}
__device__ __forceinline__ void unpack2(u64 v, float& lo, float& hi) {
    asm("mov.b64 {%0, %1}, %2;" : "=f"(lo), "=f"(hi) : "l"(v));
}
// Blackwell packed f32x2 FMA: two fp32 FMAs per issued instruction
__device__ __forceinline__ void ffma2(u64& d, u64 a, u64 b) {
    asm("fma.rn.f32x2 %0, %1, %2, %0;" : "+l"(d) : "l"(a), "l"(b));
}

__global__ __launch_bounds__(NTHREADS, 3)
void decoder_out_kernel(const float* __restrict__ x,
                        const float* __restrict__ w,
                        const float* __restrict__ bias,
                        float* __restrict__ out)
{
    const int tid    = threadIdx.x;
    const int f      = tid % FD;             // frequency lane (warp = 32 consecutive f)
    const int tg     = tid / FD;             // t-group 0/1
    const int tile   = blockIdx.x;
    const int bb     = blockIdx.y;
    const int tstart = tile * TT + tg * TPG; // first output t of this thread

    // Window row r covers t = tstart - 4 + r  (r = 0..8). Only tile 0 / tg 0 has t<0.
    const float* __restrict__ xbase = x + (size_t)bb * CD * TD * FD + f;
    long roff[WROWS];
    bool rvalid[WROWS];
#pragma unroll
    for (int r = 0; r < WROWS; ++r) {
        int t = tstart - (TC - 1) + r;
        rvalid[r] = (t >= 0);                // upper bound never exceeded (tiles cover T)
        roff[r]   = (long)t * FD;
    }

    // Weights for lane f as u64: element [c*5+k] = (w[f,c,k,0], w[f,c,k,1]); 8B-aligned.
    const u64* __restrict__ wp = reinterpret_cast<const u64*>(w) + (size_t)f * (CD * TC);

    // Accumulators: o=0 low lane, o=1 high lane; init with bias.
    u64 acc[TPG];
    {
        const float2 bv = *reinterpret_cast<const float2*>(bias + f * 2);
        const u64 bpk = pack2(bv.x, bv.y);
#pragma unroll
        for (int i = 0; i < TPG; ++i) acc[i] = bpk;
    }

#pragma unroll 2
    for (int c = 0; c < CD; ++c) {
        const float* __restrict__ xc = xbase + (size_t)c * (TD * FD);

        // 9 coalesced x loads (128B per warp per row) + 5 weight loads; batched for MLP
        float s[WROWS];
#pragma unroll
        for (int r = 0; r < WROWS; ++r)
            s[r] = rvalid[r] ? __ldg(xc + roff[r]) : 0.f;

        u64 wv[TC];
#pragma unroll
        for (int k = 0; k < TC; ++k) wv[k] = wp[c * TC + k];

        u64 xv[WROWS];
#pragma unroll
        for (int r = 0; r < WROWS; ++r) xv[r] = pack2(s[r], s[r]);

#pragma unroll
        for (int tt = 0; tt < TPG; ++tt)
#pragma unroll
            for (int k = 0; k < TC; ++k)
                ffma2(acc[tt], xv[tt + k], wv[k]);
    }

    // out[b][o][t][f]: f contiguous, t stride 96, o stride 96000, b stride 192000
    const int os = TD * FD;
    float* op = out + (size_t)bb * 2 * os + (size_t)tstart * FD + f;
#pragma unroll
    for (int tt = 0; tt < TPG; ++tt) {
        float lo, hi;
        unpack2(acc[tt], lo, hi);
        op[tt * FD]      = lo;   // o = 0
        op[os + tt * FD] = hi;   // o = 1
    }
}

extern "C" void kernel_launch(void* const* d_in, const int* in_sizes, int n_in,
                              void* d_out, int out_size)
{
    const float* x    = (const float*)d_in[0];
    const float* w    = (const float*)d_in[1];
    const float* bias = (const float*)d_in[2];
    float* out        = (float*)d_out;

    dim3 grid(NTILES, 4);   // 100 t-tiles x B=4 = 400 blocks, one full wave
    decoder_out_kernel<<<grid, NTHREADS>>>(x, w, bias, out);
}

// round 3
// speedup vs baseline: 1.5838x; 1.5838x over previous
#include <cuda_runtime.h>
#include <cstdint>

// x      [B=4, C=64, T=1000, F=96]  f32
// weight [F=96, 320, O=2] f32 (idx c*5+k) ; bias [F=96, O=2]
// out    [B=4, O=2, T=1000, F=96]  f32
// out[b,o,t,f] = sum_{c,k} x[b,c,t-4+k,f] * w[f,c*5+k,o] + bias[f,o]

#define FD 96
#define FP 48                  // f-pairs
#define CD 64
#define TD 1000
#define TC 5
#define TPG 5
#define TT 10                  // t per block (2 t-groups)
#define NTHREADS 96            // 48 f-pairs x 2 t-groups
#define NTILES (TD / TT)       // 100
#define WROWS (TPG + TC - 1)   // 9

typedef unsigned long long u64;

// Transposed weights: g_wt[fp][c][k][o] = (w[2fp,c,k,o], w[2fp+1,c,k,o]) packed u64
__device__ __align__(16) u64 g_wt[FP * CD * TC * 2];   // 245 KB
__device__ u64 g_bt[FP * 2];                            // bias pairs

__device__ __forceinline__ u64 pack2(float lo, float hi) {
    u64 r; asm("mov.b64 %0, {%1, %2};" : "=l"(r) : "f"(lo), "f"(hi)); return r;
}
__device__ __forceinline__ void ffma2(u64& d, u64 a, u64 b) {
    asm("fma.rn.f32x2 %0, %1, %2, %0;" : "+l"(d) : "l"(a), "l"(b));
}

__global__ void transpose_w(const float* __restrict__ w, const float* __restrict__ b) {
    int i = blockIdx.x * blockDim.x + threadIdx.x;       // over FP*CD*TC*2 = 30720
    if (i < FP * CD * TC * 2) {
        int fp = i / (CD * TC * 2);
        int rem = i % (CD * TC * 2);                     // = c*10 + k*2 + o
        int ck = rem >> 1, o = rem & 1;                  // ck = c*5+k
        int f = 2 * fp;
        g_wt[i] = pack2(w[(f * 320 + ck) * 2 + o], w[((f + 1) * 320 + ck) * 2 + o]);
    }
    if (i < FP * 2) {
        int fp = i >> 1, o = i & 1;
        g_bt[i] = pack2(b[(2 * fp) * 2 + o], b[(2 * fp + 1) * 2 + o]);
    }
}

__global__ __launch_bounds__(NTHREADS)
void decoder_out_kernel(const float* __restrict__ x, float* __restrict__ out)
{
    const int tid    = threadIdx.x;
    const int fp     = tid % FP;              // f-pair lane
    const int tg     = tid / FP;              // t-group 0/1
    const int bb     = blockIdx.y;
    const int tstart = blockIdx.x * TT + tg * TPG;

    // row r covers t = tstart-4+r ; invalid only for tile 0 / tg 0, r<4
    bool rv[WROWS];
#pragma unroll
    for (int r = 0; r < WROWS; ++r) rv[r] = (tstart - (TC - 1) + r) >= 0;

    // x base for this thread (may point before x for tile 0; guarded loads)
    const char* __restrict__ xb = (const char*)x +
        ((long)bb * CD * TD * FD + (long)(tstart - (TC - 1)) * FD + 2 * fp) * 4;
    const ulonglong2* __restrict__ wb =
        reinterpret_cast<const ulonglong2*>(g_wt) + fp * (CD * TC);

    // accumulators: acc[t][o], lanes = (f, f+1)
    u64 acc[TPG][2];
    {
        u64 b0 = g_bt[fp * 2 + 0], b1 = g_bt[fp * 2 + 1];
#pragma unroll
        for (int t = 0; t < TPG; ++t) { acc[t][0] = b0; acc[t][1] = b1; }
    }

    // double-buffered register stages (prefetch distance 2)
    u64        xs[2][WROWS];
    ulonglong2 ws[2][TC];

#define LOAD_STAGE(S, CC)                                                        \
    {                                                                            \
        const u64* xq = (const u64*)(xb + (size_t)(CC) * (TD * FD * 4));         \
        _Pragma("unroll")                                                        \
        for (int r = 0; r < WROWS; ++r) xs[S][r] = rv[r] ? xq[r * FP] : 0ull;    \
        const ulonglong2* wq = wb + (CC) * TC;                                   \
        _Pragma("unroll")                                                        \
        for (int k = 0; k < TC; ++k) ws[S][k] = wq[k];                           \
    }

    LOAD_STAGE(0, 0)
    LOAD_STAGE(1, 1)

#pragma unroll 2
    for (int c = 0; c < CD; ++c) {
        const int cur = c & 1;
#pragma unroll
        for (int k = 0; k < TC; ++k) {
            const u64 wk0 = ws[cur][k].x, wk1 = ws[cur][k].y;
#pragma unroll
            for (int t = 0; t < TPG; ++t) {
                ffma2(acc[t][0], xs[cur][t + k], wk0);
                ffma2(acc[t][1], xs[cur][t + k], wk1);
            }
        }
        if (c + 2 < CD) LOAD_STAGE(cur, c + 2)
    }
#undef LOAD_STAGE

    // out[b][o][t][f]: store float2 at f = 2*fp
    const size_t os = (size_t)TD * FD;
    char* op = (char*)out + ((size_t)bb * 2 * os + (size_t)tstart * FD + 2 * fp) * 4;
#pragma unroll
    for (int t = 0; t < TPG; ++t) {
        *reinterpret_cast<u64*>(op + (size_t)t * FD * 4)            = acc[t][0]; // o=0
        *reinterpret_cast<u64*>(op + (os + (size_t)t * FD) * 4)     = acc[t][1]; // o=1
    }
}

extern "C" void kernel_launch(void* const* d_in, const int* in_sizes, int n_in,
                              void* d_out, int out_size)
{
    const float* x    = (const float*)d_in[0];
    const float* w    = (const float*)d_in[1];
    const float* bias = (const float*)d_in[2];
    float* out        = (float*)d_out;

    transpose_w<<<(FP * CD * TC * 2 + 127) / 128, 128>>>(w, bias);
    dim3 grid(NTILES, 4);   // 400 blocks x 96 threads
    decoder_out_kernel<<<grid, NTHREADS>>>(x, out);
}

// round 7
// speedup vs baseline: 2.6578x; 1.6782x over previous
#include <cuda_runtime.h>
#include <cstdint>

// x      [B=4, C=64, T=1000, F=96]  f32
// weight [F=96, 320, O=2] f32 (idx ck = c*5+k) ; bias [F=96, O=2]
// out    [B=4, O=2, T=1000, F=96]  f32
// out[b,o,t,f] = sum_{c,k} x[b,c,t-4+k,f] * w[f,ck,o] + bias[f,o]

#define FD 96
#define FP 48                  // f-pairs
#define CD 64
#define TD 1000
#define TC 5
#define TPG 5
#define TT 10                  // t per block (2 t-groups)
#define NTHREADS 96            // 48 f-pairs x 2 t-groups
#define NTILES (TD / TT)       // 100
#define WROWS (TPG + TC - 1)   // 9

typedef unsigned long long u64;

// Transposed weights, WARP-COALESCED layout: g_wt[(ck*FP + fp)*2 + o]
//   = (w[2fp,ck,o], w[2fp+1,ck,o]) packed as u64 (f-pair in the two f32x2 lanes).
// For fixed ck, lanes fp=0..31 read consecutive 16B -> 4 wavefronts per warp load
// (the earlier [fp][ck][o] layout hit 32 distinct 128B lines per warp load).
__device__ __align__(16) u64 g_wt[CD * TC * FP * 2];   // 245 KB
__device__ u64 g_bt[FP * 2];                           // bias pairs

__device__ __forceinline__ u64 pack2(float lo, float hi) {
    u64 r; asm("mov.b64 %0, {%1, %2};" : "=l"(r) : "f"(lo), "f"(hi)); return r;
}
__device__ __forceinline__ void ffma2(u64& d, u64 a, u64 b) {
    asm("fma.rn.f32x2 %0, %1, %2, %0;" : "+l"(d) : "l"(a), "l"(b));
}

__global__ void transpose_w(const float* __restrict__ w, const float* __restrict__ b) {
    int i = blockIdx.x * blockDim.x + threadIdx.x;       // over CD*TC*FP*2 = 30720
    if (i < CD * TC * FP * 2) {
        int ck  = i / (FP * 2);
        int rem = i % (FP * 2);
        int fp  = rem >> 1, o = rem & 1;
        int f   = 2 * fp;
        g_wt[i] = pack2(w[(f * (CD * TC) + ck) * 2 + o],
                        w[((f + 1) * (CD * TC) + ck) * 2 + o]);
    }
    if (i < FP * 2) {
        int fp = i >> 1, o = i & 1;
        g_bt[i] = pack2(b[(2 * fp) * 2 + o], b[(2 * fp + 1) * 2 + o]);
    }
}

// Register-stage loader (prefetch distance 2); plain function instead of macro.
__device__ __forceinline__ void load_stage(u64* xs, ulonglong2* ws,
                                           const char* __restrict__ xb,
                                           const ulonglong2* __restrict__ wb,
                                           const bool* rv, int cc)
{
    const u64* __restrict__ xq = (const u64*)(xb + (size_t)cc * (TD * FD * 4));
#pragma unroll
    for (int r = 0; r < WROWS; ++r) xs[r] = rv[r] ? xq[r * FP] : 0ull;
#pragma unroll
    for (int k = 0; k < TC; ++k) ws[k] = wb[(cc * TC + k) * FP];
}

__global__ __launch_bounds__(NTHREADS)
void decoder_out_kernel(const float* __restrict__ x, float* __restrict__ out)
{
    const int tid    = threadIdx.x;
    const int fp     = tid % FP;              // f-pair lane
    const int tg     = tid / FP;              // t-group 0/1
    const int bb     = blockIdx.y;
    const int tstart = blockIdx.x * TT + tg * TPG;

    // row r covers t = tstart-4+r ; invalid only for tile 0 / tg 0, r<4
    bool rv[WROWS];
#pragma unroll
    for (int r = 0; r < WROWS; ++r) rv[r] = (tstart - (TC - 1) + r) >= 0;

    // x base for this thread (may point before x for tile 0; guarded loads)
    const char* __restrict__ xb = (const char*)x +
        ((long)bb * CD * TD * FD + (long)(tstart - (TC - 1)) * FD + 2 * fp) * 4;
    const ulonglong2* __restrict__ wb =
        reinterpret_cast<const ulonglong2*>(g_wt) + fp;   // + (c*TC+k)*FP per element

    // accumulators: acc[t][o], lanes = (f, f+1)
    u64 acc[TPG][2];
    {
        u64 b0 = g_bt[fp * 2 + 0], b1 = g_bt[fp * 2 + 1];
#pragma unroll
        for (int t = 0; t < TPG; ++t) { acc[t][0] = b0; acc[t][1] = b1; }
    }

    // double-buffered register stages (prefetch distance 2)
    u64        xs[2][WROWS];
    ulonglong2 ws[2][TC];

    load_stage(xs[0], ws[0], xb, wb, rv, 0);
    load_stage(xs[1], ws[1], xb, wb, rv, 1);

#pragma unroll 2
    for (int c = 0; c < CD; ++c) {
        const int cur = c & 1;
#pragma unroll
        for (int k = 0; k < TC; ++k) {
            const u64 wk0 = ws[cur][k].x, wk1 = ws[cur][k].y;
#pragma unroll
            for (int t = 0; t < TPG; ++t) {
                ffma2(acc[t][0], xs[cur][t + k], wk0);
                ffma2(acc[t][1], xs[cur][t + k], wk1);
            }
        }
        if (c + 2 < CD) load_stage(xs[cur], ws[cur], xb, wb, rv, c + 2);
    }

    // out[b][o][t][f]: store float2 at f = 2*fp
    const size_t os = (size_t)TD * FD;
    char* op = (char*)out + ((size_t)bb * 2 * os + (size_t)tstart * FD + 2 * fp) * 4;
#pragma unroll
    for (int t = 0; t < TPG; ++t) {
        *reinterpret_cast<u64*>(op + (size_t)t * FD * 4)        = acc[t][0]; // o=0
        *reinterpret_cast<u64*>(op + (os + (size_t)t * FD) * 4) = acc[t][1]; // o=1
    }
}

extern "C" void kernel_launch(void* const* d_in, const int* in_sizes, int n_in,
                              void* d_out, int out_size)
{
    const float* x    = (const float*)d_in[0];
    const float* w    = (const float*)d_in[1];
    const float* bias = (const float*)d_in[2];
    float* out        = (float*)d_out;

    transpose_w<<<(CD * TC * FP * 2 + 127) / 128, 128>>>(w, bias);
    dim3 grid(NTILES, 4);   // 400 blocks x 96 threads
    decoder_out_kernel<<<grid, NTHREADS>>>(x, out);
}

// round 8
// speedup vs baseline: 2.9436x; 1.1075x over previous
#include <cuda_runtime.h>
#include <cstdint>

// x      [B=4, C=64, T=1000, F=96]  f32
// weight [F=96, 320, O=2] f32 (idx ck = c*5+k) ; bias [F=96, O=2]
// out    [B=4, O=2, T=1000, F=96]  f32
// out[b,o,t,f] = sum_{c,k} x[b,c,t-4+k,f] * w[f,ck,o] + bias[f,o]

#define FD 96
#define FP 48                  // f-pairs
#define CD 64
#define TD 1000
#define TC 5
#define TPG 5
#define TT 10                  // t per block (2 t-groups)
#define CG 2                   // c-groups per block (C split 2x32)
#define CPG (CD / CG)          // 32 c per group
#define NTHREADS (CG * 96)     // 192
#define NTILES (TD / TT)       // 100
#define WROWS (TPG + TC - 1)   // 9

typedef unsigned long long u64;

// Warp-coalesced transposed weights: g_wt[(ck*FP + fp)*2 + o]
//   = (w[2fp,ck,o], w[2fp+1,ck,o]) packed u64 (f-pair in the two f32x2 lanes).
__device__ __align__(16) u64 g_wt[CD * TC * FP * 2];   // 245 KB
__device__ u64 g_bt[FP * 2];                           // bias pairs

__device__ __forceinline__ u64 pack2(float lo, float hi) {
    u64 r; asm("mov.b64 %0, {%1, %2};" : "=l"(r) : "f"(lo), "f"(hi)); return r;
}
__device__ __forceinline__ void ffma2(u64& d, u64 a, u64 b) {
    asm("fma.rn.f32x2 %0, %1, %2, %0;" : "+l"(d) : "l"(a), "l"(b));
}
__device__ __forceinline__ void fadd2(u64& d, u64 a) {
    asm("add.rn.f32x2 %0, %0, %1;" : "+l"(d) : "l"(a));
}

__global__ void transpose_w(const float* __restrict__ w, const float* __restrict__ b) {
    int i = blockIdx.x * blockDim.x + threadIdx.x;       // over CD*TC*FP*2 = 30720
    if (i < CD * TC * FP * 2) {
        int ck  = i / (FP * 2);
        int rem = i % (FP * 2);
        int fp  = rem >> 1, o = rem & 1;
        int f   = 2 * fp;
        g_wt[i] = pack2(w[(f * (CD * TC) + ck) * 2 + o],
                        w[((f + 1) * (CD * TC) + ck) * 2 + o]);
    }
    if (i < FP * 2) {
        int fp = i >> 1, o = i & 1;
        g_bt[i] = pack2(b[(2 * fp) * 2 + o], b[(2 * fp + 1) * 2 + o]);
    }
}

// Register-stage loader (prefetch distance 2).
__device__ __forceinline__ void load_stage(u64* xs, ulonglong2* ws,
                                           const char* __restrict__ xb,
                                           const ulonglong2* __restrict__ wb,
                                           const bool* rv, int cc)
{
    const u64* __restrict__ xq = (const u64*)(xb + (size_t)cc * (TD * FD * 4));
#pragma unroll
    for (int r = 0; r < WROWS; ++r) xs[r] = rv[r] ? xq[r * FP] : 0ull;
#pragma unroll
    for (int k = 0; k < TC; ++k) ws[k] = wb[(cc * TC + k) * FP];
}

__global__ __launch_bounds__(NTHREADS)
void decoder_out_kernel(const float* __restrict__ x, float* __restrict__ out)
{
    // partial sums from c-group 1: [t][tg][fp] (lane-sequential -> conflict-free)
    __shared__ __align__(16) ulonglong2 part[TPG * 2 * FP];

    const int tid    = threadIdx.x;
    const int cg     = tid / 96;              // c-group 0/1
    const int sub    = tid % 96;
    const int fp     = sub % FP;              // f-pair lane
    const int tg     = sub / FP;              // t-group 0/1
    const int bb     = blockIdx.y;
    const int tstart = blockIdx.x * TT + tg * TPG;

    // row r covers t = tstart-4+r ; invalid only for tile 0 / tg 0, r<4
    bool rv[WROWS];
#pragma unroll
    for (int r = 0; r < WROWS; ++r) rv[r] = (tstart - (TC - 1) + r) >= 0;

    // x base for this thread's c-range (may point before x for tile 0; guarded)
    const char* __restrict__ xb = (const char*)x +
        ((long)bb * CD * TD * FD + (long)cg * CPG * TD * FD +
         (long)(tstart - (TC - 1)) * FD + 2 * fp) * 4;
    const ulonglong2* __restrict__ wb =
        reinterpret_cast<const ulonglong2*>(g_wt) + (size_t)cg * CPG * TC * FP + fp;

    // accumulators: acc[t][o], lanes = (f, f+1); group 0 carries the bias
    u64 acc[TPG][2];
    {
        u64 b0 = 0ull, b1 = 0ull;
        if (cg == 0) { b0 = g_bt[fp * 2 + 0]; b1 = g_bt[fp * 2 + 1]; }
#pragma unroll
        for (int t = 0; t < TPG; ++t) { acc[t][0] = b0; acc[t][1] = b1; }
    }

    // double-buffered register stages (prefetch distance 2)
    u64        xs[2][WROWS];
    ulonglong2 ws[2][TC];

    load_stage(xs[0], ws[0], xb, wb, rv, 0);
    load_stage(xs[1], ws[1], xb, wb, rv, 1);

#pragma unroll 2
    for (int c = 0; c < CPG; ++c) {
        const int cur = c & 1;
#pragma unroll
        for (int k = 0; k < TC; ++k) {
            const u64 wk0 = ws[cur][k].x, wk1 = ws[cur][k].y;
#pragma unroll
            for (int t = 0; t < TPG; ++t) {
                ffma2(acc[t][0], xs[cur][t + k], wk0);
                ffma2(acc[t][1], xs[cur][t + k], wk1);
            }
        }
        if (c + 2 < CPG) load_stage(xs[cur], ws[cur], xb, wb, rv, c + 2);
    }

    // cross-group reduction through shared memory (single sync)
    if (cg == 1) {
#pragma unroll
        for (int t = 0; t < TPG; ++t)
            part[(t * 2 + tg) * FP + fp] = make_ulonglong2(acc[t][0], acc[t][1]);
    }
    __syncthreads();
    if (cg == 0) {
        const size_t os = (size_t)TD * FD;
        char* op = (char*)out +
            ((size_t)bb * 2 * os + (size_t)tstart * FD + 2 * fp) * 4;
#pragma unroll
        for (int t = 0; t < TPG; ++t) {
            ulonglong2 p = part[(t * 2 + tg) * FP + fp];
            fadd2(acc[t][0], p.x);
            fadd2(acc[t][1], p.y);
            *reinterpret_cast<u64*>(op + (size_t)t * FD * 4)        = acc[t][0]; // o=0
            *reinterpret_cast<u64*>(op + (os + (size_t)t * FD) * 4) = acc[t][1]; // o=1
        }
    }
}

extern "C" void kernel_launch(void* const* d_in, const int* in_sizes, int n_in,
                              void* d_out, int out_size)
{
    const float* x    = (const float*)d_in[0];
    const float* w    = (const float*)d_in[1];
    const float* bias = (const float*)d_in[2];
    float* out        = (float*)d_out;

    transpose_w<<<(CD * TC * FP * 2 + 127) / 128, 128>>>(w, bias);
    dim3 grid(NTILES, 4);   // 400 blocks x 192 threads, one wave
    decoder_out_kernel<<<grid, NTHREADS>>>(x, out);
}